// round 13
// baseline (speedup 1.0000x reference)
#include <cuda_runtime.h>
#include <cuda_fp16.h>
#include <math.h>
#include <stdint.h>

// Problem constants
#define MM 8192           // B*L tokens
#define EE 1024
#define VV 64
#define NTT 2016
#define LN_EPS 1e-5f
#define MC (MM / 2)       // half chunk

// ---------------------------------------------------------------------------
// Scratch (device globals; no dynamic allocation allowed)
// ---------------------------------------------------------------------------
__device__ float g_h[(size_t)MM * EE];          // gelu output (pre-LN)
__device__ float g_theta[(size_t)MM * NTT];     // softplus(Theta)
__device__ __half g_hx_hi[(size_t)MM * EE];
__device__ __half g_h_hi [(size_t)MM * EE];
__device__ __half g_Wd_hi[EE * EE],  g_Wd_lo[EE * EE];
__device__ __half g_Wt_hi[VV * EE],  g_Wt_lo[VV * EE];
__device__ __half g_WT_hi[NTT * EE], g_WT_lo[NTT * EE];

// ---------------------------------------------------------------------------
// PTX helpers
// ---------------------------------------------------------------------------
__device__ __forceinline__ uint32_t smem_u32(const void* p) {
    return (uint32_t)__cvta_generic_to_shared(p);
}
__device__ __forceinline__ void cp16(uint32_t dst, const void* src, int sz) {
    asm volatile("cp.async.cg.shared.global [%0], [%1], 16, %2;"
                 :: "r"(dst), "l"(src), "r"(sz));
}
__device__ __forceinline__ void cp_commit() {
    asm volatile("cp.async.commit_group;" ::: "memory");
}
template<int N> __device__ __forceinline__ void cp_wait() {
    asm volatile("cp.async.wait_group %0;" :: "n"(N) : "memory");
}
__device__ __forceinline__ void ldsm4(uint32_t* r, uint32_t a) {
    asm volatile("ldmatrix.sync.aligned.m8n8.x4.shared.b16 {%0,%1,%2,%3}, [%4];"
        : "=r"(r[0]), "=r"(r[1]), "=r"(r[2]), "=r"(r[3]) : "r"(a));
}
__device__ __forceinline__ void mma16816(float* c, const uint32_t* a,
                                         uint32_t b0, uint32_t b1) {
    asm volatile(
        "mma.sync.aligned.m16n8k16.row.col.f32.f16.f16.f32 "
        "{%0,%1,%2,%3}, {%4,%5,%6,%7}, {%8,%9}, {%0,%1,%2,%3};"
        : "+f"(c[0]), "+f"(c[1]), "+f"(c[2]), "+f"(c[3])
        : "r"(a[0]), "r"(a[1]), "r"(a[2]), "r"(a[3]), "r"(b0), "r"(b1));
}

// ---------------------------------------------------------------------------
// fp32 -> (fp16 hi, fp16 lo) split, 8 elems/thread (uint4 stores)
// ---------------------------------------------------------------------------
__global__ __launch_bounds__(256)
void split_kernel(const float* __restrict__ x, __half* __restrict__ hi,
                  __half* __restrict__ lo, int n8)
{
    int i = blockIdx.x * 256 + threadIdx.x;
    if (i >= n8) return;
    float4 a = ((const float4*)x)[i * 2];
    float4 b = ((const float4*)x)[i * 2 + 1];
    float vv[8] = {a.x, a.y, a.z, a.w, b.x, b.y, b.z, b.w};
    __half h[8], l[8];
#pragma unroll
    for (int k = 0; k < 8; ++k) {
        h[k] = __float2half_rn(vv[k]);
        l[k] = __float2half_rn(vv[k] - __half2float(h[k]));
    }
    ((uint4*)hi)[i] = *(uint4*)h;
    ((uint4*)lo)[i] = *(uint4*)l;
}

// fp32 -> fp16 hi only (for A operands of 2-term GEMMs)
__global__ __launch_bounds__(256)
void split_hi_kernel(const float* __restrict__ x, __half* __restrict__ hi, int n8)
{
    int i = blockIdx.x * 256 + threadIdx.x;
    if (i >= n8) return;
    float4 a = ((const float4*)x)[i * 2];
    float4 b = ((const float4*)x)[i * 2 + 1];
    float vv[8] = {a.x, a.y, a.z, a.w, b.x, b.y, b.z, b.w};
    __half h[8];
#pragma unroll
    for (int k = 0; k < 8; ++k) h[k] = __float2half_rn(vv[k]);
    ((uint4*)hi)[i] = *(uint4*)h;
}

// ---------------------------------------------------------------------------
// fp16 multi-term HMMA GEMM:  C[M,N] = epi(A[M,K] @ B[N,K]^T + bias[N])
// BM=128, BN template (256 big / 64 narrow), BK=64, 512 threads (16 warps).
// TERMS=3: Ah*Bh + Ah*Bl + Al*Bh ; TERMS=2: Ah*Bh + Ah*Bl
// cp.async double-buffered smem, padded 144B rows.
// EPI: 0 none, 1 exact gelu, 2 softplus
// ---------------------------------------------------------------------------
#define HBM 128
#define HBK 64
#define HROWB 144                 // 64 fp16 = 128B + 16B pad

template<int EPI, int BN, int WN, int TERMS>
__global__ __launch_bounds__(512, 1)
void gemm_hmma(const __half* __restrict__ Ah, const __half* __restrict__ Al,
               const __half* __restrict__ Bh, const __half* __restrict__ Bl,
               const float* __restrict__ bias, float* __restrict__ C,
               int N, int K)
{
    constexpr int WM  = 16 / WN;
    constexpr int WTM = HBM / WM;
    constexpr int WTN = BN / WN;
    constexpr int MT  = WTM / 16;
    constexpr int NJ  = WTN / 16;

    constexpr int A_BYTES = HBM * HROWB;
    constexpr int B_BYTES = BN * HROWB;
    constexpr int AHOFF = 0;
    constexpr int ALOFF = A_BYTES;
    constexpr int BHOFF = 2 * A_BYTES;
    constexpr int BLOFF = 2 * A_BYTES + B_BYTES;
    constexpr int STAGE = 2 * A_BYTES + 2 * B_BYTES;

    extern __shared__ char hsm[];
    const uint32_t sb = smem_u32(hsm);

    const int tid  = threadIdx.x;
    const int wid  = tid >> 5;
    const int lane = tid & 31;
    const int wmb  = (wid % WM) * WTM;
    const int wnb  = (wid / WM) * WTN;
    const int bm   = blockIdx.x * HBM;
    const int bn   = blockIdx.y * BN;

    auto issue_stage = [&](int kt) {
        const uint32_t st = sb + (kt & 1) * STAGE;
        const int k0 = kt * HBK;
#pragma unroll
        for (int it = 0; it < 2; ++it) {
            int c = tid + it * 512;
            int row = c >> 3, part = c & 7;
            uint32_t dst = (uint32_t)(row * HROWB + part * 16);
            size_t src = (size_t)(bm + row) * K + k0 + part * 8;
            cp16(st + AHOFF + dst, Ah + src, 16);
            if (TERMS == 3) cp16(st + ALOFF + dst, Al + src, 16);
        }
#pragma unroll
        for (int it = 0; it < BN / 64; ++it) {
            int c = tid + it * 512;
            int row = c >> 3, part = c & 7;
            int gn = bn + row;
            int valid = (gn < N) ? 16 : 0;
            int gnc = (gn < N) ? gn : 0;
            uint32_t dst = (uint32_t)(row * HROWB + part * 16);
            size_t src = (size_t)gnc * K + k0 + part * 8;
            cp16(st + BHOFF + dst, Bh + src, valid);
            cp16(st + BLOFF + dst, Bl + src, valid);
        }
        cp_commit();
    };

    float acc[MT][WTN / 8][4];
#pragma unroll
    for (int i = 0; i < MT; ++i)
#pragma unroll
        for (int j = 0; j < WTN / 8; ++j)
#pragma unroll
            for (int q = 0; q < 4; ++q) acc[i][j][q] = 0.0f;

    issue_stage(0);

    const int nk = K / HBK;
    const int a_row = lane & 15;
    const int a_cb  = (lane >> 4) * 16;
    const int b_row = ((lane >> 4) ? 8 : 0) + (lane & 7);
    const int b_cb  = (((lane >> 3) & 1) ? 16 : 0);

    for (int kt = 0; kt < nk; ++kt) {
        if (kt + 1 < nk) { issue_stage(kt + 1); cp_wait<1>(); }
        else             { cp_wait<0>(); }
        __syncthreads();
        const uint32_t st = sb + (kt & 1) * STAGE;

#pragma unroll
        for (int ks = 0; ks < 4; ++ks) {
            uint32_t aH[MT][4], aL[MT][4];
#pragma unroll
            for (int mt = 0; mt < MT; ++mt) {
                const uint32_t ao = st + (uint32_t)((wmb + mt * 16 + a_row) * HROWB
                                                    + ks * 32 + a_cb);
                ldsm4(aH[mt], ao + AHOFF);
                if (TERMS == 3) ldsm4(aL[mt], ao + ALOFF);
            }
#pragma unroll
            for (int jj = 0; jj < NJ; ++jj) {
                const uint32_t bo = st + (uint32_t)((wnb + jj * 16 + b_row) * HROWB
                                                    + ks * 32 + b_cb);
                uint32_t bH[4], bL[4];
                ldsm4(bH, bo + BHOFF);
                ldsm4(bL, bo + BLOFF);
#pragma unroll
                for (int mt = 0; mt < MT; ++mt) {
#pragma unroll
                    for (int sub = 0; sub < 2; ++sub) {
                        float* c = acc[mt][jj * 2 + sub];
                        mma16816(c, aH[mt], bH[sub * 2], bH[sub * 2 + 1]);
                        mma16816(c, aH[mt], bL[sub * 2], bL[sub * 2 + 1]);
                        if (TERMS == 3)
                            mma16816(c, aL[mt], bH[sub * 2], bH[sub * 2 + 1]);
                    }
                }
            }
        }
        __syncthreads();
    }

    // epilogue
#pragma unroll
    for (int mt = 0; mt < MT; ++mt) {
        const int row = bm + wmb + mt * 16 + (lane >> 2);
#pragma unroll
        for (int nt = 0; nt < WTN / 8; ++nt) {
            const int col = bn + wnb + nt * 8 + (lane & 3) * 2;
            if (col < N) {
                const float b0 = bias[col], b1 = bias[col + 1];
                float vals[4];
                vals[0] = acc[mt][nt][0] + b0;
                vals[1] = acc[mt][nt][1] + b1;
                vals[2] = acc[mt][nt][2] + b0;
                vals[3] = acc[mt][nt][3] + b1;
#pragma unroll
                for (int q = 0; q < 4; ++q) {
                    float x = vals[q];
                    if (EPI == 1) {
                        x = 0.5f * x * (1.0f + erff(x * 0.70710678118654752440f));
                    } else if (EPI == 2) {
                        x = fmaxf(x, 0.0f) + log1pf(expf(-fabsf(x)));
                    }
                    vals[q] = x;
                }
                *(float2*)&C[(size_t)row * N + col]       = make_float2(vals[0], vals[1]);
                *(float2*)&C[(size_t)(row + 8) * N + col] = make_float2(vals[2], vals[3]);
            }
        }
    }
}

// ---------------------------------------------------------------------------
// LayerNorm over rows of E=1024, fused with fp16 hi-only conversion.
// ---------------------------------------------------------------------------
__global__ __launch_bounds__(128)
void ln_hi_kernel(const float* __restrict__ h, const float* __restrict__ g,
                  const float* __restrict__ b, __half* __restrict__ hi)
{
    const int row = blockIdx.x;
    const int tid = threadIdx.x;
    const int wid = tid >> 5;
    const float* p = h + (size_t)row * EE;

    float4 v0 = ((const float4*)p)[tid * 2];
    float4 v1 = ((const float4*)p)[tid * 2 + 1];
    float v[8] = {v0.x, v0.y, v0.z, v0.w, v1.x, v1.y, v1.z, v1.w};

    __shared__ float red_a[4], red_b[4];

    float s = 0.0f;
#pragma unroll
    for (int k = 0; k < 8; ++k) s += v[k];
#pragma unroll
    for (int o = 16; o; o >>= 1) s += __shfl_xor_sync(0xffffffffu, s, o);
    if ((tid & 31) == 0) red_a[wid] = s;
    __syncthreads();
    const float mu = (red_a[0] + red_a[1] + red_a[2] + red_a[3]) * (1.0f / EE);

    float d[8];
    float s2 = 0.0f;
#pragma unroll
    for (int k = 0; k < 8; ++k) { d[k] = v[k] - mu; s2 += d[k] * d[k]; }
#pragma unroll
    for (int o = 16; o; o >>= 1) s2 += __shfl_xor_sync(0xffffffffu, s2, o);
    if ((tid & 31) == 0) red_b[wid] = s2;
    __syncthreads();
    const float rstd = rsqrtf((red_b[0] + red_b[1] + red_b[2] + red_b[3]) * (1.0f / EE)
                              + LN_EPS);

    const int c = tid * 8;
    float4 g0 = *(const float4*)&g[c], g1 = *(const float4*)&g[c + 4];
    float4 b0 = *(const float4*)&b[c], b1 = *(const float4*)&b[c + 4];
    float gg[8] = {g0.x, g0.y, g0.z, g0.w, g1.x, g1.y, g1.z, g1.w};
    float bb[8] = {b0.x, b0.y, b0.z, b0.w, b1.x, b1.y, b1.z, b1.w};

    __half hb[8];
#pragma unroll
    for (int k = 0; k < 8; ++k)
        hb[k] = __float2half_rn(d[k] * rstd * gg[k] + bb[k]);
    ((uint4*)(hi + (size_t)row * EE))[tid] = *(uint4*)hb;
}

// ---------------------------------------------------------------------------
// Softmax (in-place) over rows of V=64. One warp per row, 8 rows per block.
// ---------------------------------------------------------------------------
__global__ __launch_bounds__(256)
void softmax_kernel(float* __restrict__ logits)
{
    const int row = blockIdx.x * 8 + (threadIdx.x >> 5);
    const int lane = threadIdx.x & 31;
    float* p = logits + (size_t)row * VV;

    float2 v = *(const float2*)&p[lane * 2];
    float m = fmaxf(v.x, v.y);
#pragma unroll
    for (int o = 16; o; o >>= 1) m = fmaxf(m, __shfl_xor_sync(0xffffffffu, m, o));
    float e0 = expf(v.x - m), e1 = expf(v.y - m);
    float s = e0 + e1;
#pragma unroll
    for (int o = 16; o; o >>= 1) s += __shfl_xor_sync(0xffffffffu, s, o);
    float inv = 1.0f / s;
    float2 o2; o2.x = e0 * inv; o2.y = e1 * inv;
    *(float2*)&p[lane * 2] = o2;
}

// ---------------------------------------------------------------------------
// Q assembly (float4 stores)
// ---------------------------------------------------------------------------
__global__ __launch_bounds__(256)
void qasm_kernel(const float* __restrict__ theta, const float* __restrict__ pi,
                 float* __restrict__ Q)
{
    const int tok = blockIdx.x;
    __shared__ float th[NTT];
    __shared__ float spi[VV];
    __shared__ float rspi[VV];

    const int tid = threadIdx.x;
    const float* tp = theta + (size_t)tok * NTT;
    for (int i = tid; i < NTT / 4; i += 256)
        ((float4*)th)[i] = ((const float4*)tp)[i];
    if (tid < VV) {
        float p = pi[(size_t)tok * VV + tid];
        float sp = sqrtf(p);
        spi[tid] = sp;
        rspi[tid] = 1.0f / sp;
    }
    __syncthreads();

    const int i = tid >> 2;
    const int jb = (tid & 3) * 16;
    const float ri = rspi[i];
    const int offi = i * (127 - i) / 2;

    float vals[16];
    float s = 0.0f;
#pragma unroll
    for (int jj = 0; jj < 16; ++jj) {
        int j = jb + jj;
        float sv;
        if (j == i)      sv = 0.0f;
        else if (i < j)  sv = th[offi + j - i - 1];
        else             sv = th[j * (127 - j) / 2 + i - j - 1];
        float qv = sv * spi[j] * ri;
        vals[jj] = qv;
        s += qv;
    }
    s += __shfl_xor_sync(0xffffffffu, s, 1);
    s += __shfl_xor_sync(0xffffffffu, s, 2);

    if (i >= jb && i < jb + 16) vals[i - jb] = -s;

    float4* out4 = (float4*)(Q + (size_t)tok * (VV * VV) + i * VV + jb);
#pragma unroll
    for (int q = 0; q < 4; ++q)
        out4[q] = make_float4(vals[q * 4], vals[q * 4 + 1],
                              vals[q * 4 + 2], vals[q * 4 + 3]);
}

// ---------------------------------------------------------------------------
// Launch: exact round-9 schedule (411.5us best); LN writes hi only and GEMM2
// is 2-term (h_lo eliminated everywhere).
// ---------------------------------------------------------------------------
#define SMEM_BIG  (2 * (2 * 128 * HROWB + 2 * 256 * HROWB))   // 221184
#define SMEM_SMALL (2 * (2 * 128 * HROWB + 2 * 64 * HROWB))   // 110592

static cudaEvent_t mk_event() {
    cudaEvent_t e; cudaEventCreateWithFlags(&e, cudaEventDisableTiming); return e;
}

extern "C" void kernel_launch(void* const* d_in, const int* in_sizes, int n_in,
                              void* d_out, int out_size)
{
    const float* hx = (const float*)d_in[0];   // (B,L,E)
    const float* Wd = (const float*)d_in[1];   // (E,E)
    const float* bd = (const float*)d_in[2];
    const float* lg = (const float*)d_in[3];
    const float* lb = (const float*)d_in[4];
    const float* Wt = (const float*)d_in[5];   // (V,E)
    const float* bt = (const float*)d_in[6];
    const float* WT = (const float*)d_in[7];   // (NT,E)
    const float* bT = (const float*)d_in[8];

    float* out = (float*)d_out;
    float* Q  = out;
    float* pi = out + (size_t)MM * VV * VV;

    float *hbuf, *thbuf;
    __half *hxh, *hh, *wdh, *wdl, *wth, *wtl, *wTh, *wTl;
    cudaGetSymbolAddress((void**)&hbuf,  g_h);
    cudaGetSymbolAddress((void**)&thbuf, g_theta);
    cudaGetSymbolAddress((void**)&hxh, g_hx_hi);
    cudaGetSymbolAddress((void**)&hh,  g_h_hi);
    cudaGetSymbolAddress((void**)&wdh, g_Wd_hi);  cudaGetSymbolAddress((void**)&wdl, g_Wd_lo);
    cudaGetSymbolAddress((void**)&wth, g_Wt_hi);  cudaGetSymbolAddress((void**)&wtl, g_Wt_lo);
    cudaGetSymbolAddress((void**)&wTh, g_WT_hi);  cudaGetSymbolAddress((void**)&wTl, g_WT_lo);

    cudaFuncSetAttribute((const void*)gemm_hmma<1, 256, 4, 2>,
                         cudaFuncAttributeMaxDynamicSharedMemorySize, SMEM_BIG);
    cudaFuncSetAttribute((const void*)gemm_hmma<2, 256, 4, 2>,
                         cudaFuncAttributeMaxDynamicSharedMemorySize, SMEM_BIG);
    cudaFuncSetAttribute((const void*)gemm_hmma<0, 64, 2, 2>,
                         cudaFuncAttributeMaxDynamicSharedMemorySize, SMEM_SMALL);

    static cudaStream_t s1 = []{
        cudaStream_t s; cudaStreamCreateWithFlags(&s, cudaStreamNonBlocking); return s;
    }();
    static cudaEvent_t evFork = mk_event();
    static cudaEvent_t eX1 = mk_event();      // hx c1 split (s1)
    static cudaEvent_t evWT = mk_event();     // Wt+WT splits (s1)
    static cudaEvent_t e10 = mk_event();      // GEMM1 c0 (S0)
    static cudaEvent_t e11 = mk_event();      // GEMM1 c1 (S0)
    static cudaEvent_t eL0 = mk_event();      // LN c0 (s1)
    static cudaEvent_t eL1 = mk_event();      // LN c1 (s1)
    static cudaEvent_t eS1 = mk_event();      // softmax c1 (s1)
    static cudaEvent_t e30 = mk_event();      // GEMM3 c0 (S0)
    static cudaEvent_t eQ0 = mk_event();      // qasm c0 (s1)

    const size_t offE = (size_t)MC * EE;
    const size_t offT = (size_t)MC * NTT;
    const size_t offV = (size_t)MC * VV;
    const size_t offQ = (size_t)MC * VV * VV;

    // fork
    cudaEventRecord(evFork, 0);
    cudaStreamWaitEvent(s1, evFork, 0);

    // s1: hx c1 split, then GEMM2/GEMM3 weight splits
    split_hi_kernel<<<(MC * EE / 8 + 255) / 256, 256, 0, s1>>>(
        hx + offE, hxh + offE, MC * EE / 8);
    cudaEventRecord(eX1, s1);
    split_kernel<<<(VV * EE / 8 + 255) / 256, 256, 0, s1>>>(Wt, wth, wtl, VV * EE / 8);
    split_kernel<<<(NTT * EE / 8 + 255) / 256, 256, 0, s1>>>(WT, wTh, wTl, NTT * EE / 8);
    cudaEventRecord(evWT, s1);

    // S0: Wd split + hx c0 split -> GEMM1 c0 -> GEMM1 c1
    split_kernel<<<(EE * EE / 8 + 255) / 256, 256>>>(Wd, wdh, wdl, EE * EE / 8);
    split_hi_kernel<<<(MC * EE / 8 + 255) / 256, 256>>>(hx, hxh, MC * EE / 8);
    gemm_hmma<1, 256, 4, 2><<<dim3(MC / HBM, EE / 256), 512, SMEM_BIG>>>(
        hxh, hxh, wdh, wdl, bd, hbuf, EE, EE);
    cudaEventRecord(e10, 0);
    cudaStreamWaitEvent(0, eX1, 0);
    gemm_hmma<1, 256, 4, 2><<<dim3(MC / HBM, EE / 256), 512, SMEM_BIG>>>(
        hxh + offE, hxh + offE, wdh, wdl, bd, hbuf + offE, EE, EE);
    cudaEventRecord(e11, 0);

    // s1: LN per half chunk (c0 overlaps GEMM1 c1), then GEMM2 + softmax per half
    cudaStreamWaitEvent(s1, e10, 0);
    ln_hi_kernel<<<MC, 128, 0, s1>>>(hbuf, lg, lb, hh);
    cudaEventRecord(eL0, s1);
    cudaStreamWaitEvent(s1, e11, 0);
    ln_hi_kernel<<<MC, 128, 0, s1>>>(hbuf + offE, lg, lb, hh + offE);
    cudaEventRecord(eL1, s1);
    gemm_hmma<0, 64, 2, 2><<<dim3(MC / HBM, 1), 512, SMEM_SMALL, s1>>>(
        hh, hh, wth, wtl, bt, pi, VV, EE);
    gemm_hmma<0, 64, 2, 2><<<dim3(MC / HBM, 1), 512, SMEM_SMALL, s1>>>(
        hh + offE, hh + offE, wth, wtl, bt, pi + offV, VV, EE);
    softmax_kernel<<<MC / 8, 256, 0, s1>>>(pi);
    softmax_kernel<<<MC / 8, 256, 0, s1>>>(pi + offV);
    cudaEventRecord(eS1, s1);

    // S0: GEMM3 per half chunk
    cudaStreamWaitEvent(0, evWT, 0);
    cudaStreamWaitEvent(0, eL0, 0);
    gemm_hmma<2, 256, 4, 2><<<dim3(MC / HBM, (NTT + 255) / 256), 512, SMEM_BIG>>>(
        hh, hh, wTh, wTl, bT, thbuf, NTT, EE);
    cudaEventRecord(e30, 0);
    cudaStreamWaitEvent(0, eL1, 0);
    gemm_hmma<2, 256, 4, 2><<<dim3(MC / HBM, (NTT + 255) / 256), 512, SMEM_BIG>>>(
        hh + offE, hh + offE, wTh, wTl, bT, thbuf + offT, NTT, EE);

    // s1: qasm c0 (overlaps GEMM3 c1 on S0; softmax c0 precedes in s1 order)
    cudaStreamWaitEvent(s1, e30, 0);
    qasm_kernel<<<MC, 256, 0, s1>>>(thbuf, pi, Q);
    cudaEventRecord(eQ0, s1);

    // S0: qasm c1 after GEMM3 c1 (program order) + softmax c1; then join
    cudaStreamWaitEvent(0, eS1, 0);
    qasm_kernel<<<MC, 256>>>(thbuf + offT, pi + offV, Q + offQ);
    cudaStreamWaitEvent(0, eQ0, 0);
}

// round 14
// speedup vs baseline: 1.5324x; 1.5324x over previous
#include <cuda_runtime.h>
#include <cuda_fp16.h>
#include <math.h>
#include <stdint.h>

// Problem constants
#define MM 8192           // B*L tokens
#define EE 1024
#define VV 64
#define NTT 2016
#define LN_EPS 1e-5f
#define MC (MM / 2)       // half chunk

// ---------------------------------------------------------------------------
// Scratch (device globals; no dynamic allocation allowed)
// ---------------------------------------------------------------------------
__device__ float g_h[(size_t)MM * EE];          // gelu output (pre-LN)
__device__ float g_theta[(size_t)MM * NTT];     // softplus(Theta)
__device__ __half g_hx_hi[(size_t)MM * EE];
__device__ __half g_h_hi [(size_t)MM * EE], g_h_lo [(size_t)MM * EE];
__device__ __half g_Wd_hi[EE * EE],  g_Wd_lo[EE * EE];
__device__ __half g_Wt_hi[VV * EE],  g_Wt_lo[VV * EE];
__device__ __half g_WT_hi[NTT * EE], g_WT_lo[NTT * EE];

// ---------------------------------------------------------------------------
// PTX helpers
// ---------------------------------------------------------------------------
__device__ __forceinline__ uint32_t smem_u32(const void* p) {
    return (uint32_t)__cvta_generic_to_shared(p);
}
__device__ __forceinline__ void cp16(uint32_t dst, const void* src, int sz) {
    asm volatile("cp.async.cg.shared.global [%0], [%1], 16, %2;"
                 :: "r"(dst), "l"(src), "r"(sz));
}
__device__ __forceinline__ void cp_commit() {
    asm volatile("cp.async.commit_group;" ::: "memory");
}
template<int N> __device__ __forceinline__ void cp_wait() {
    asm volatile("cp.async.wait_group %0;" :: "n"(N) : "memory");
}
__device__ __forceinline__ void ldsm4(uint32_t* r, uint32_t a) {
    asm volatile("ldmatrix.sync.aligned.m8n8.x4.shared.b16 {%0,%1,%2,%3}, [%4];"
        : "=r"(r[0]), "=r"(r[1]), "=r"(r[2]), "=r"(r[3]) : "r"(a));
}
__device__ __forceinline__ void mma16816(float* c, const uint32_t* a,
                                         uint32_t b0, uint32_t b1) {
    asm volatile(
        "mma.sync.aligned.m16n8k16.row.col.f32.f16.f16.f32 "
        "{%0,%1,%2,%3}, {%4,%5,%6,%7}, {%8,%9}, {%0,%1,%2,%3};"
        : "+f"(c[0]), "+f"(c[1]), "+f"(c[2]), "+f"(c[3])
        : "r"(a[0]), "r"(a[1]), "r"(a[2]), "r"(a[3]), "r"(b0), "r"(b1));
}

// ---------------------------------------------------------------------------
// fp32 -> (fp16 hi, fp16 lo) split, 8 elems/thread (uint4 stores)
// ---------------------------------------------------------------------------
__global__ __launch_bounds__(256)
void split_kernel(const float* __restrict__ x, __half* __restrict__ hi,
                  __half* __restrict__ lo, int n8)
{
    int i = blockIdx.x * 256 + threadIdx.x;
    if (i >= n8) return;
    float4 a = ((const float4*)x)[i * 2];
    float4 b = ((const float4*)x)[i * 2 + 1];
    float vv[8] = {a.x, a.y, a.z, a.w, b.x, b.y, b.z, b.w};
    __half h[8], l[8];
#pragma unroll
    for (int k = 0; k < 8; ++k) {
        h[k] = __float2half_rn(vv[k]);
        l[k] = __float2half_rn(vv[k] - __half2float(h[k]));
    }
    ((uint4*)hi)[i] = *(uint4*)h;
    ((uint4*)lo)[i] = *(uint4*)l;
}

// fp32 -> fp16 hi only (for A operands of 2-term GEMMs)
__global__ __launch_bounds__(256)
void split_hi_kernel(const float* __restrict__ x, __half* __restrict__ hi, int n8)
{
    int i = blockIdx.x * 256 + threadIdx.x;
    if (i >= n8) return;
    float4 a = ((const float4*)x)[i * 2];
    float4 b = ((const float4*)x)[i * 2 + 1];
    float vv[8] = {a.x, a.y, a.z, a.w, b.x, b.y, b.z, b.w};
    __half h[8];
#pragma unroll
    for (int k = 0; k < 8; ++k) h[k] = __float2half_rn(vv[k]);
    ((uint4*)hi)[i] = *(uint4*)h;
}

// ---------------------------------------------------------------------------
// fp16 multi-term HMMA GEMM:  C[M,N] = epi(A[M,K] @ B[N,K]^T + bias[N])
// BM=128, BN template (256 big / 64 narrow), BK=64, 512 threads (16 warps).
// TERMS=3: Ah*Bh + Ah*Bl + Al*Bh ; TERMS=2: Ah*Bh + Ah*Bl
// cp.async double-buffered smem, padded 144B rows.
// EPI: 0 none, 1 exact gelu, 2 softplus
// ---------------------------------------------------------------------------
#define HBM 128
#define HBK 64
#define HROWB 144                 // 64 fp16 = 128B + 16B pad

template<int EPI, int BN, int WN, int TERMS>
__global__ __launch_bounds__(512, 1)
void gemm_hmma(const __half* __restrict__ Ah, const __half* __restrict__ Al,
               const __half* __restrict__ Bh, const __half* __restrict__ Bl,
               const float* __restrict__ bias, float* __restrict__ C,
               int N, int K)
{
    constexpr int WM  = 16 / WN;
    constexpr int WTM = HBM / WM;
    constexpr int WTN = BN / WN;
    constexpr int MT  = WTM / 16;
    constexpr int NJ  = WTN / 16;

    constexpr int A_BYTES = HBM * HROWB;
    constexpr int B_BYTES = BN * HROWB;
    constexpr int AHOFF = 0;
    constexpr int ALOFF = A_BYTES;
    constexpr int BHOFF = 2 * A_BYTES;
    constexpr int BLOFF = 2 * A_BYTES + B_BYTES;
    constexpr int STAGE = 2 * A_BYTES + 2 * B_BYTES;

    extern __shared__ char hsm[];
    const uint32_t sb = smem_u32(hsm);

    const int tid  = threadIdx.x;
    const int wid  = tid >> 5;
    const int lane = tid & 31;
    const int wmb  = (wid % WM) * WTM;
    const int wnb  = (wid / WM) * WTN;
    const int bm   = blockIdx.x * HBM;
    const int bn   = blockIdx.y * BN;

    auto issue_stage = [&](int kt) {
        const uint32_t st = sb + (kt & 1) * STAGE;
        const int k0 = kt * HBK;
#pragma unroll
        for (int it = 0; it < 2; ++it) {
            int c = tid + it * 512;
            int row = c >> 3, part = c & 7;
            uint32_t dst = (uint32_t)(row * HROWB + part * 16);
            size_t src = (size_t)(bm + row) * K + k0 + part * 8;
            cp16(st + AHOFF + dst, Ah + src, 16);
            if (TERMS == 3) cp16(st + ALOFF + dst, Al + src, 16);
        }
#pragma unroll
        for (int it = 0; it < BN / 64; ++it) {
            int c = tid + it * 512;
            int row = c >> 3, part = c & 7;
            int gn = bn + row;
            int valid = (gn < N) ? 16 : 0;
            int gnc = (gn < N) ? gn : 0;
            uint32_t dst = (uint32_t)(row * HROWB + part * 16);
            size_t src = (size_t)gnc * K + k0 + part * 8;
            cp16(st + BHOFF + dst, Bh + src, valid);
            cp16(st + BLOFF + dst, Bl + src, valid);
        }
        cp_commit();
    };

    float acc[MT][WTN / 8][4];
#pragma unroll
    for (int i = 0; i < MT; ++i)
#pragma unroll
        for (int j = 0; j < WTN / 8; ++j)
#pragma unroll
            for (int q = 0; q < 4; ++q) acc[i][j][q] = 0.0f;

    issue_stage(0);

    const int nk = K / HBK;
    const int a_row = lane & 15;
    const int a_cb  = (lane >> 4) * 16;
    const int b_row = ((lane >> 4) ? 8 : 0) + (lane & 7);
    const int b_cb  = (((lane >> 3) & 1) ? 16 : 0);

    for (int kt = 0; kt < nk; ++kt) {
        if (kt + 1 < nk) { issue_stage(kt + 1); cp_wait<1>(); }
        else             { cp_wait<0>(); }
        __syncthreads();
        const uint32_t st = sb + (kt & 1) * STAGE;

#pragma unroll
        for (int ks = 0; ks < 4; ++ks) {
            uint32_t aH[MT][4], aL[MT][4];
#pragma unroll
            for (int mt = 0; mt < MT; ++mt) {
                const uint32_t ao = st + (uint32_t)((wmb + mt * 16 + a_row) * HROWB
                                                    + ks * 32 + a_cb);
                ldsm4(aH[mt], ao + AHOFF);
                if (TERMS == 3) ldsm4(aL[mt], ao + ALOFF);
            }
#pragma unroll
            for (int jj = 0; jj < NJ; ++jj) {
                const uint32_t bo = st + (uint32_t)((wnb + jj * 16 + b_row) * HROWB
                                                    + ks * 32 + b_cb);
                uint32_t bH[4], bL[4];
                ldsm4(bH, bo + BHOFF);
                ldsm4(bL, bo + BLOFF);
#pragma unroll
                for (int mt = 0; mt < MT; ++mt) {
#pragma unroll
                    for (int sub = 0; sub < 2; ++sub) {
                        float* c = acc[mt][jj * 2 + sub];
                        mma16816(c, aH[mt], bH[sub * 2], bH[sub * 2 + 1]);
                        mma16816(c, aH[mt], bL[sub * 2], bL[sub * 2 + 1]);
                        if (TERMS == 3)
                            mma16816(c, aL[mt], bH[sub * 2], bH[sub * 2 + 1]);
                    }
                }
            }
        }
        __syncthreads();
    }

    // epilogue
#pragma unroll
    for (int mt = 0; mt < MT; ++mt) {
        const int row = bm + wmb + mt * 16 + (lane >> 2);
#pragma unroll
        for (int nt = 0; nt < WTN / 8; ++nt) {
            const int col = bn + wnb + nt * 8 + (lane & 3) * 2;
            if (col < N) {
                const float b0 = bias[col], b1 = bias[col + 1];
                float vals[4];
                vals[0] = acc[mt][nt][0] + b0;
                vals[1] = acc[mt][nt][1] + b1;
                vals[2] = acc[mt][nt][2] + b0;
                vals[3] = acc[mt][nt][3] + b1;
#pragma unroll
                for (int q = 0; q < 4; ++q) {
                    float x = vals[q];
                    if (EPI == 1) {
                        x = 0.5f * x * (1.0f + erff(x * 0.70710678118654752440f));
                    } else if (EPI == 2) {
                        x = fmaxf(x, 0.0f) + log1pf(expf(-fabsf(x)));
                    }
                    vals[q] = x;
                }
                *(float2*)&C[(size_t)row * N + col]       = make_float2(vals[0], vals[1]);
                *(float2*)&C[(size_t)(row + 8) * N + col] = make_float2(vals[2], vals[3]);
            }
        }
    }
}

// ---------------------------------------------------------------------------
// LayerNorm over rows of E=1024, fused with fp16 hi/lo split of the output.
// ---------------------------------------------------------------------------
__global__ __launch_bounds__(128)
void ln_split_kernel(const float* __restrict__ h, const float* __restrict__ g,
                     const float* __restrict__ b,
                     __half* __restrict__ hi, __half* __restrict__ lo)
{
    const int row = blockIdx.x;
    const int tid = threadIdx.x;
    const int wid = tid >> 5;
    const float* p = h + (size_t)row * EE;

    float4 v0 = ((const float4*)p)[tid * 2];
    float4 v1 = ((const float4*)p)[tid * 2 + 1];
    float v[8] = {v0.x, v0.y, v0.z, v0.w, v1.x, v1.y, v1.z, v1.w};

    __shared__ float red_a[4], red_b[4];

    float s = 0.0f;
#pragma unroll
    for (int k = 0; k < 8; ++k) s += v[k];
#pragma unroll
    for (int o = 16; o; o >>= 1) s += __shfl_xor_sync(0xffffffffu, s, o);
    if ((tid & 31) == 0) red_a[wid] = s;
    __syncthreads();
    const float mu = (red_a[0] + red_a[1] + red_a[2] + red_a[3]) * (1.0f / EE);

    float d[8];
    float s2 = 0.0f;
#pragma unroll
    for (int k = 0; k < 8; ++k) { d[k] = v[k] - mu; s2 += d[k] * d[k]; }
#pragma unroll
    for (int o = 16; o; o >>= 1) s2 += __shfl_xor_sync(0xffffffffu, s2, o);
    if ((tid & 31) == 0) red_b[wid] = s2;
    __syncthreads();
    const float rstd = rsqrtf((red_b[0] + red_b[1] + red_b[2] + red_b[3]) * (1.0f / EE)
                              + LN_EPS);

    const int c = tid * 8;
    float4 g0 = *(const float4*)&g[c], g1 = *(const float4*)&g[c + 4];
    float4 b0 = *(const float4*)&b[c], b1 = *(const float4*)&b[c + 4];
    float gg[8] = {g0.x, g0.y, g0.z, g0.w, g1.x, g1.y, g1.z, g1.w};
    float bb[8] = {b0.x, b0.y, b0.z, b0.w, b1.x, b1.y, b1.z, b1.w};

    __half hb[8], lb8[8];
#pragma unroll
    for (int k = 0; k < 8; ++k) {
        float o = d[k] * rstd * gg[k] + bb[k];
        hb[k]  = __float2half_rn(o);
        lb8[k] = __float2half_rn(o - __half2float(hb[k]));
    }
    ((uint4*)(hi + (size_t)row * EE))[tid] = *(uint4*)hb;
    ((uint4*)(lo + (size_t)row * EE))[tid] = *(uint4*)lb8;
}

// ---------------------------------------------------------------------------
// Softmax (in-place) over rows of V=64. One warp per row, 8 rows per block.
// ---------------------------------------------------------------------------
__global__ __launch_bounds__(256)
void softmax_kernel(float* __restrict__ logits)
{
    const int row = blockIdx.x * 8 + (threadIdx.x >> 5);
    const int lane = threadIdx.x & 31;
    float* p = logits + (size_t)row * VV;

    float2 v = *(const float2*)&p[lane * 2];
    float m = fmaxf(v.x, v.y);
#pragma unroll
    for (int o = 16; o; o >>= 1) m = fmaxf(m, __shfl_xor_sync(0xffffffffu, m, o));
    float e0 = expf(v.x - m), e1 = expf(v.y - m);
    float s = e0 + e1;
#pragma unroll
    for (int o = 16; o; o >>= 1) s += __shfl_xor_sync(0xffffffffu, s, o);
    float inv = 1.0f / s;
    float2 o2; o2.x = e0 * inv; o2.y = e1 * inv;
    *(float2*)&p[lane * 2] = o2;
}

// ---------------------------------------------------------------------------
// Q assembly (float4 stores)
// ---------------------------------------------------------------------------
__global__ __launch_bounds__(256)
void qasm_kernel(const float* __restrict__ theta, const float* __restrict__ pi,
                 float* __restrict__ Q)
{
    const int tok = blockIdx.x;
    __shared__ float th[NTT];
    __shared__ float spi[VV];
    __shared__ float rspi[VV];

    const int tid = threadIdx.x;
    const float* tp = theta + (size_t)tok * NTT;
    for (int i = tid; i < NTT / 4; i += 256)
        ((float4*)th)[i] = ((const float4*)tp)[i];
    if (tid < VV) {
        float p = pi[(size_t)tok * VV + tid];
        float sp = sqrtf(p);
        spi[tid] = sp;
        rspi[tid] = 1.0f / sp;
    }
    __syncthreads();

    const int i = tid >> 2;
    const int jb = (tid & 3) * 16;
    const float ri = rspi[i];
    const int offi = i * (127 - i) / 2;

    float vals[16];
    float s = 0.0f;
#pragma unroll
    for (int jj = 0; jj < 16; ++jj) {
        int j = jb + jj;
        float sv;
        if (j == i)      sv = 0.0f;
        else if (i < j)  sv = th[offi + j - i - 1];
        else             sv = th[j * (127 - j) / 2 + i - j - 1];
        float qv = sv * spi[j] * ri;
        vals[jj] = qv;
        s += qv;
    }
    s += __shfl_xor_sync(0xffffffffu, s, 1);
    s += __shfl_xor_sync(0xffffffffu, s, 2);

    if (i >= jb && i < jb + 16) vals[i - jb] = -s;

    float4* out4 = (float4*)(Q + (size_t)tok * (VV * VV) + i * VV + jb);
#pragma unroll
    for (int q = 0; q < 4; ++q)
        out4[q] = make_float4(vals[q * 4], vals[q * 4 + 1],
                              vals[q * 4 + 2], vals[q * 4 + 3]);
}

// ---------------------------------------------------------------------------
// Launch: 2-chunk software pipeline across two streams (round-9 champion).
// ---------------------------------------------------------------------------
#define SMEM_BIG  (2 * (2 * 128 * HROWB + 2 * 256 * HROWB))   // 221184
#define SMEM_SMALL (2 * (2 * 128 * HROWB + 2 * 64 * HROWB))   // 110592

static cudaEvent_t mk_event() {
    cudaEvent_t e; cudaEventCreateWithFlags(&e, cudaEventDisableTiming); return e;
}

extern "C" void kernel_launch(void* const* d_in, const int* in_sizes, int n_in,
                              void* d_out, int out_size)
{
    const float* hx = (const float*)d_in[0];   // (B,L,E)
    const float* Wd = (const float*)d_in[1];   // (E,E)
    const float* bd = (const float*)d_in[2];
    const float* lg = (const float*)d_in[3];
    const float* lb = (const float*)d_in[4];
    const float* Wt = (const float*)d_in[5];   // (V,E)
    const float* bt = (const float*)d_in[6];
    const float* WT = (const float*)d_in[7];   // (NT,E)
    const float* bT = (const float*)d_in[8];

    float* out = (float*)d_out;
    float* Q  = out;
    float* pi = out + (size_t)MM * VV * VV;

    float *hbuf, *thbuf;
    __half *hxh, *hh, *hl, *wdh, *wdl, *wth, *wtl, *wTh, *wTl;
    cudaGetSymbolAddress((void**)&hbuf,  g_h);
    cudaGetSymbolAddress((void**)&thbuf, g_theta);
    cudaGetSymbolAddress((void**)&hxh, g_hx_hi);
    cudaGetSymbolAddress((void**)&hh,  g_h_hi);   cudaGetSymbolAddress((void**)&hl,  g_h_lo);
    cudaGetSymbolAddress((void**)&wdh, g_Wd_hi);  cudaGetSymbolAddress((void**)&wdl, g_Wd_lo);
    cudaGetSymbolAddress((void**)&wth, g_Wt_hi);  cudaGetSymbolAddress((void**)&wtl, g_Wt_lo);
    cudaGetSymbolAddress((void**)&wTh, g_WT_hi);  cudaGetSymbolAddress((void**)&wTl, g_WT_lo);

    cudaFuncSetAttribute((const void*)gemm_hmma<1, 256, 4, 2>,
                         cudaFuncAttributeMaxDynamicSharedMemorySize, SMEM_BIG);
    cudaFuncSetAttribute((const void*)gemm_hmma<2, 256, 4, 2>,
                         cudaFuncAttributeMaxDynamicSharedMemorySize, SMEM_BIG);
    cudaFuncSetAttribute((const void*)gemm_hmma<0, 64, 2, 3>,
                         cudaFuncAttributeMaxDynamicSharedMemorySize, SMEM_SMALL);

    static cudaStream_t s1 = []{
        cudaStream_t s; cudaStreamCreateWithFlags(&s, cudaStreamNonBlocking); return s;
    }();
    static cudaEvent_t evFork = mk_event();
    static cudaEvent_t eX1 = mk_event();      // hx c1 split (s1)
    static cudaEvent_t evWT = mk_event();     // Wt+WT splits (s1)
    static cudaEvent_t e10 = mk_event();      // GEMM1 c0 (S0)
    static cudaEvent_t e11 = mk_event();      // GEMM1 c1 (S0)
    static cudaEvent_t eL0 = mk_event();      // LN c0 (s1)
    static cudaEvent_t eL1 = mk_event();      // LN c1 (s1)
    static cudaEvent_t eS1 = mk_event();      // softmax c1 (s1)
    static cudaEvent_t e30 = mk_event();      // GEMM3 c0 (S0)
    static cudaEvent_t eQ0 = mk_event();      // qasm c0 (s1)

    const size_t offE = (size_t)MC * EE;
    const size_t offT = (size_t)MC * NTT;
    const size_t offV = (size_t)MC * VV;
    const size_t offQ = (size_t)MC * VV * VV;

    // fork
    cudaEventRecord(evFork, 0);
    cudaStreamWaitEvent(s1, evFork, 0);

    // s1: hx c1 split, then GEMM2/GEMM3 weight splits
    split_hi_kernel<<<(MC * EE / 8 + 255) / 256, 256, 0, s1>>>(
        hx + offE, hxh + offE, MC * EE / 8);
    cudaEventRecord(eX1, s1);
    split_kernel<<<(VV * EE / 8 + 255) / 256, 256, 0, s1>>>(Wt, wth, wtl, VV * EE / 8);
    split_kernel<<<(NTT * EE / 8 + 255) / 256, 256, 0, s1>>>(WT, wTh, wTl, NTT * EE / 8);
    cudaEventRecord(evWT, s1);

    // S0: Wd split + hx c0 split -> GEMM1 c0 -> GEMM1 c1
    split_kernel<<<(EE * EE / 8 + 255) / 256, 256>>>(Wd, wdh, wdl, EE * EE / 8);
    split_hi_kernel<<<(MC * EE / 8 + 255) / 256, 256>>>(hx, hxh, MC * EE / 8);
    gemm_hmma<1, 256, 4, 2><<<dim3(MC / HBM, EE / 256), 512, SMEM_BIG>>>(
        hxh, hxh, wdh, wdl, bd, hbuf, EE, EE);
    cudaEventRecord(e10, 0);
    cudaStreamWaitEvent(0, eX1, 0);
    gemm_hmma<1, 256, 4, 2><<<dim3(MC / HBM, EE / 256), 512, SMEM_BIG>>>(
        hxh + offE, hxh + offE, wdh, wdl, bd, hbuf + offE, EE, EE);
    cudaEventRecord(e11, 0);

    // s1: LN per half chunk (c0 overlaps GEMM1 c1), then GEMM2 + softmax per half
    cudaStreamWaitEvent(s1, e10, 0);
    ln_split_kernel<<<MC, 128, 0, s1>>>(hbuf, lg, lb, hh, hl);
    cudaEventRecord(eL0, s1);
    cudaStreamWaitEvent(s1, e11, 0);
    ln_split_kernel<<<MC, 128, 0, s1>>>(hbuf + offE, lg, lb, hh + offE, hl + offE);
    cudaEventRecord(eL1, s1);
    gemm_hmma<0, 64, 2, 3><<<dim3(MC / HBM, 1), 512, SMEM_SMALL, s1>>>(
        hh, hl, wth, wtl, bt, pi, VV, EE);
    gemm_hmma<0, 64, 2, 3><<<dim3(MC / HBM, 1), 512, SMEM_SMALL, s1>>>(
        hh + offE, hl + offE, wth, wtl, bt, pi + offV, VV, EE);
    softmax_kernel<<<MC / 8, 256, 0, s1>>>(pi);
    softmax_kernel<<<MC / 8, 256, 0, s1>>>(pi + offV);
    cudaEventRecord(eS1, s1);

    // S0: GEMM3 per half chunk
    cudaStreamWaitEvent(0, evWT, 0);
    cudaStreamWaitEvent(0, eL0, 0);
    gemm_hmma<2, 256, 4, 2><<<dim3(MC / HBM, (NTT + 255) / 256), 512, SMEM_BIG>>>(
        hh, hh, wTh, wTl, bT, thbuf, NTT, EE);
    cudaEventRecord(e30, 0);
    cudaStreamWaitEvent(0, eL1, 0);
    gemm_hmma<2, 256, 4, 2><<<dim3(MC / HBM, (NTT + 255) / 256), 512, SMEM_BIG>>>(
        hh + offE, hh + offE, wTh, wTl, bT, thbuf + offT, NTT, EE);

    // s1: qasm c0 (overlaps GEMM3 c1 on S0; softmax c0 precedes in s1 order)
    cudaStreamWaitEvent(s1, e30, 0);
    qasm_kernel<<<MC, 256, 0, s1>>>(thbuf, pi, Q);
    cudaEventRecord(eQ0, s1);

    // S0: qasm c1 after GEMM3 c1 (program order) + softmax c1; then join
    cudaStreamWaitEvent(0, eS1, 0);
    qasm_kernel<<<MC, 256>>>(thbuf + offT, pi + offV, Q + offQ);
    cudaStreamWaitEvent(0, eQ0, 0);
}

// round 15
// speedup vs baseline: 1.5413x; 1.0058x over previous
#include <cuda_runtime.h>
#include <cuda_fp16.h>
#include <math.h>
#include <stdint.h>

// Problem constants
#define MM 8192           // B*L tokens
#define EE 1024
#define VV 64
#define NTT 2016
#define LN_EPS 1e-5f
#define MC (MM / 2)       // half chunk

// ---------------------------------------------------------------------------
// Scratch (device globals; no dynamic allocation allowed)
// ---------------------------------------------------------------------------
__device__ float g_h[(size_t)MM * EE];          // gelu output (pre-LN)
__device__ float g_theta[(size_t)MM * NTT];     // softplus(Theta)
__device__ __half g_hx_hi[(size_t)MM * EE];
__device__ __half g_h_hi [(size_t)MM * EE], g_h_lo [(size_t)MM * EE];
__device__ __half g_Wd_hi[EE * EE],  g_Wd_lo[EE * EE];
__device__ __half g_Wt_hi[VV * EE],  g_Wt_lo[VV * EE];
__device__ __half g_WT_hi[NTT * EE], g_WT_lo[NTT * EE];

// ---------------------------------------------------------------------------
// PTX helpers
// ---------------------------------------------------------------------------
__device__ __forceinline__ uint32_t smem_u32(const void* p) {
    return (uint32_t)__cvta_generic_to_shared(p);
}
__device__ __forceinline__ void cp16(uint32_t dst, const void* src, int sz) {
    asm volatile("cp.async.cg.shared.global [%0], [%1], 16, %2;"
                 :: "r"(dst), "l"(src), "r"(sz));
}
__device__ __forceinline__ void cp_commit() {
    asm volatile("cp.async.commit_group;" ::: "memory");
}
template<int N> __device__ __forceinline__ void cp_wait() {
    asm volatile("cp.async.wait_group %0;" :: "n"(N) : "memory");
}
__device__ __forceinline__ void ldsm4(uint32_t* r, uint32_t a) {
    asm volatile("ldmatrix.sync.aligned.m8n8.x4.shared.b16 {%0,%1,%2,%3}, [%4];"
        : "=r"(r[0]), "=r"(r[1]), "=r"(r[2]), "=r"(r[3]) : "r"(a));
}
__device__ __forceinline__ void mma16816(float* c, const uint32_t* a,
                                         uint32_t b0, uint32_t b1) {
    asm volatile(
        "mma.sync.aligned.m16n8k16.row.col.f32.f16.f16.f32 "
        "{%0,%1,%2,%3}, {%4,%5,%6,%7}, {%8,%9}, {%0,%1,%2,%3};"
        : "+f"(c[0]), "+f"(c[1]), "+f"(c[2]), "+f"(c[3])
        : "r"(a[0]), "r"(a[1]), "r"(a[2]), "r"(a[3]), "r"(b0), "r"(b1));
}

// ---------------------------------------------------------------------------
// fp32 -> (fp16 hi, fp16 lo) split, 8 elems/thread (uint4 stores)
// ---------------------------------------------------------------------------
__global__ __launch_bounds__(256)
void split_kernel(const float* __restrict__ x, __half* __restrict__ hi,
                  __half* __restrict__ lo, int n8)
{
    int i = blockIdx.x * 256 + threadIdx.x;
    if (i >= n8) return;
    float4 a = ((const float4*)x)[i * 2];
    float4 b = ((const float4*)x)[i * 2 + 1];
    float vv[8] = {a.x, a.y, a.z, a.w, b.x, b.y, b.z, b.w};
    __half h[8], l[8];
#pragma unroll
    for (int k = 0; k < 8; ++k) {
        h[k] = __float2half_rn(vv[k]);
        l[k] = __float2half_rn(vv[k] - __half2float(h[k]));
    }
    ((uint4*)hi)[i] = *(uint4*)h;
    ((uint4*)lo)[i] = *(uint4*)l;
}

// fp32 -> fp16 hi only (for A operands of 2-term GEMMs)
__global__ __launch_bounds__(256)
void split_hi_kernel(const float* __restrict__ x, __half* __restrict__ hi, int n8)
{
    int i = blockIdx.x * 256 + threadIdx.x;
    if (i >= n8) return;
    float4 a = ((const float4*)x)[i * 2];
    float4 b = ((const float4*)x)[i * 2 + 1];
    float vv[8] = {a.x, a.y, a.z, a.w, b.x, b.y, b.z, b.w};
    __half h[8];
#pragma unroll
    for (int k = 0; k < 8; ++k) h[k] = __float2half_rn(vv[k]);
    ((uint4*)hi)[i] = *(uint4*)h;
}

// ---------------------------------------------------------------------------
// fp16 multi-term HMMA GEMM:  C[M,N] = epi(A[M,K] @ B[N,K]^T + bias[N])
// BM=128, BN template (256 big / 64 narrow), BK=64, 512 threads (16 warps).
// TERMS=3: Ah*Bh + Ah*Bl + Al*Bh ; TERMS=2: Ah*Bh + Ah*Bl
// cp.async double-buffered smem, padded 144B rows.
// EPI: 0 none, 1 exact gelu, 2 softplus
// ---------------------------------------------------------------------------
#define HBM 128
#define HBK 64
#define HROWB 144                 // 64 fp16 = 128B + 16B pad

template<int EPI, int BN, int WN, int TERMS>
__global__ __launch_bounds__(512, 1)
void gemm_hmma(const __half* __restrict__ Ah, const __half* __restrict__ Al,
               const __half* __restrict__ Bh, const __half* __restrict__ Bl,
               const float* __restrict__ bias, float* __restrict__ C,
               int N, int K)
{
    constexpr int WM  = 16 / WN;
    constexpr int WTM = HBM / WM;
    constexpr int WTN = BN / WN;
    constexpr int MT  = WTM / 16;
    constexpr int NJ  = WTN / 16;

    constexpr int A_BYTES = HBM * HROWB;
    constexpr int B_BYTES = BN * HROWB;
    constexpr int AHOFF = 0;
    constexpr int ALOFF = A_BYTES;
    constexpr int BHOFF = 2 * A_BYTES;
    constexpr int BLOFF = 2 * A_BYTES + B_BYTES;
    constexpr int STAGE = 2 * A_BYTES + 2 * B_BYTES;

    extern __shared__ char hsm[];
    const uint32_t sb = smem_u32(hsm);

    const int tid  = threadIdx.x;
    const int wid  = tid >> 5;
    const int lane = tid & 31;
    const int wmb  = (wid % WM) * WTM;
    const int wnb  = (wid / WM) * WTN;
    const int bm   = blockIdx.x * HBM;
    const int bn   = blockIdx.y * BN;

    auto issue_stage = [&](int kt) {
        const uint32_t st = sb + (kt & 1) * STAGE;
        const int k0 = kt * HBK;
#pragma unroll
        for (int it = 0; it < 2; ++it) {
            int c = tid + it * 512;
            int row = c >> 3, part = c & 7;
            uint32_t dst = (uint32_t)(row * HROWB + part * 16);
            size_t src = (size_t)(bm + row) * K + k0 + part * 8;
            cp16(st + AHOFF + dst, Ah + src, 16);
            if (TERMS == 3) cp16(st + ALOFF + dst, Al + src, 16);
        }
#pragma unroll
        for (int it = 0; it < BN / 64; ++it) {
            int c = tid + it * 512;
            int row = c >> 3, part = c & 7;
            int gn = bn + row;
            int valid = (gn < N) ? 16 : 0;
            int gnc = (gn < N) ? gn : 0;
            uint32_t dst = (uint32_t)(row * HROWB + part * 16);
            size_t src = (size_t)gnc * K + k0 + part * 8;
            cp16(st + BHOFF + dst, Bh + src, valid);
            cp16(st + BLOFF + dst, Bl + src, valid);
        }
        cp_commit();
    };

    float acc[MT][WTN / 8][4];
#pragma unroll
    for (int i = 0; i < MT; ++i)
#pragma unroll
        for (int j = 0; j < WTN / 8; ++j)
#pragma unroll
            for (int q = 0; q < 4; ++q) acc[i][j][q] = 0.0f;

    issue_stage(0);

    const int nk = K / HBK;
    const int a_row = lane & 15;
    const int a_cb  = (lane >> 4) * 16;
    const int b_row = ((lane >> 4) ? 8 : 0) + (lane & 7);
    const int b_cb  = (((lane >> 3) & 1) ? 16 : 0);

    for (int kt = 0; kt < nk; ++kt) {
        if (kt + 1 < nk) { issue_stage(kt + 1); cp_wait<1>(); }
        else             { cp_wait<0>(); }
        __syncthreads();
        const uint32_t st = sb + (kt & 1) * STAGE;

#pragma unroll
        for (int ks = 0; ks < 4; ++ks) {
            uint32_t aH[MT][4], aL[MT][4];
#pragma unroll
            for (int mt = 0; mt < MT; ++mt) {
                const uint32_t ao = st + (uint32_t)((wmb + mt * 16 + a_row) * HROWB
                                                    + ks * 32 + a_cb);
                ldsm4(aH[mt], ao + AHOFF);
                if (TERMS == 3) ldsm4(aL[mt], ao + ALOFF);
            }
#pragma unroll
            for (int jj = 0; jj < NJ; ++jj) {
                const uint32_t bo = st + (uint32_t)((wnb + jj * 16 + b_row) * HROWB
                                                    + ks * 32 + b_cb);
                uint32_t bH[4], bL[4];
                ldsm4(bH, bo + BHOFF);
                ldsm4(bL, bo + BLOFF);
#pragma unroll
                for (int mt = 0; mt < MT; ++mt) {
#pragma unroll
                    for (int sub = 0; sub < 2; ++sub) {
                        float* c = acc[mt][jj * 2 + sub];
                        mma16816(c, aH[mt], bH[sub * 2], bH[sub * 2 + 1]);
                        mma16816(c, aH[mt], bL[sub * 2], bL[sub * 2 + 1]);
                        if (TERMS == 3)
                            mma16816(c, aL[mt], bH[sub * 2], bH[sub * 2 + 1]);
                    }
                }
            }
        }
        __syncthreads();
    }

    // epilogue
#pragma unroll
    for (int mt = 0; mt < MT; ++mt) {
        const int row = bm + wmb + mt * 16 + (lane >> 2);
#pragma unroll
        for (int nt = 0; nt < WTN / 8; ++nt) {
            const int col = bn + wnb + nt * 8 + (lane & 3) * 2;
            if (col < N) {
                const float b0 = bias[col], b1 = bias[col + 1];
                float vals[4];
                vals[0] = acc[mt][nt][0] + b0;
                vals[1] = acc[mt][nt][1] + b1;
                vals[2] = acc[mt][nt][2] + b0;
                vals[3] = acc[mt][nt][3] + b1;
#pragma unroll
                for (int q = 0; q < 4; ++q) {
                    float x = vals[q];
                    if (EPI == 1) {
                        x = 0.5f * x * (1.0f + erff(x * 0.70710678118654752440f));
                    } else if (EPI == 2) {
                        x = fmaxf(x, 0.0f) + log1pf(expf(-fabsf(x)));
                    }
                    vals[q] = x;
                }
                *(float2*)&C[(size_t)row * N + col]       = make_float2(vals[0], vals[1]);
                *(float2*)&C[(size_t)(row + 8) * N + col] = make_float2(vals[2], vals[3]);
            }
        }
    }
}

// ---------------------------------------------------------------------------
// LayerNorm over rows of E=1024, fused with fp16 hi/lo split of the output.
// ---------------------------------------------------------------------------
__global__ __launch_bounds__(128)
void ln_split_kernel(const float* __restrict__ h, const float* __restrict__ g,
                     const float* __restrict__ b,
                     __half* __restrict__ hi, __half* __restrict__ lo)
{
    const int row = blockIdx.x;
    const int tid = threadIdx.x;
    const int wid = tid >> 5;
    const float* p = h + (size_t)row * EE;

    float4 v0 = ((const float4*)p)[tid * 2];
    float4 v1 = ((const float4*)p)[tid * 2 + 1];
    float v[8] = {v0.x, v0.y, v0.z, v0.w, v1.x, v1.y, v1.z, v1.w};

    __shared__ float red_a[4], red_b[4];

    float s = 0.0f;
#pragma unroll
    for (int k = 0; k < 8; ++k) s += v[k];
#pragma unroll
    for (int o = 16; o; o >>= 1) s += __shfl_xor_sync(0xffffffffu, s, o);
    if ((tid & 31) == 0) red_a[wid] = s;
    __syncthreads();
    const float mu = (red_a[0] + red_a[1] + red_a[2] + red_a[3]) * (1.0f / EE);

    float d[8];
    float s2 = 0.0f;
#pragma unroll
    for (int k = 0; k < 8; ++k) { d[k] = v[k] - mu; s2 += d[k] * d[k]; }
#pragma unroll
    for (int o = 16; o; o >>= 1) s2 += __shfl_xor_sync(0xffffffffu, s2, o);
    if ((tid & 31) == 0) red_b[wid] = s2;
    __syncthreads();
    const float rstd = rsqrtf((red_b[0] + red_b[1] + red_b[2] + red_b[3]) * (1.0f / EE)
                              + LN_EPS);

    const int c = tid * 8;
    float4 g0 = *(const float4*)&g[c], g1 = *(const float4*)&g[c + 4];
    float4 b0 = *(const float4*)&b[c], b1 = *(const float4*)&b[c + 4];
    float gg[8] = {g0.x, g0.y, g0.z, g0.w, g1.x, g1.y, g1.z, g1.w};
    float bb[8] = {b0.x, b0.y, b0.z, b0.w, b1.x, b1.y, b1.z, b1.w};

    __half hb[8], lb8[8];
#pragma unroll
    for (int k = 0; k < 8; ++k) {
        float o = d[k] * rstd * gg[k] + bb[k];
        hb[k]  = __float2half_rn(o);
        lb8[k] = __float2half_rn(o - __half2float(hb[k]));
    }
    ((uint4*)(hi + (size_t)row * EE))[tid] = *(uint4*)hb;
    ((uint4*)(lo + (size_t)row * EE))[tid] = *(uint4*)lb8;
}

// ---------------------------------------------------------------------------
// Softmax (in-place) over rows of V=64. One warp per row, 8 rows per block.
// ---------------------------------------------------------------------------
__global__ __launch_bounds__(256)
void softmax_kernel(float* __restrict__ logits)
{
    const int row = blockIdx.x * 8 + (threadIdx.x >> 5);
    const int lane = threadIdx.x & 31;
    float* p = logits + (size_t)row * VV;

    float2 v = *(const float2*)&p[lane * 2];
    float m = fmaxf(v.x, v.y);
#pragma unroll
    for (int o = 16; o; o >>= 1) m = fmaxf(m, __shfl_xor_sync(0xffffffffu, m, o));
    float e0 = expf(v.x - m), e1 = expf(v.y - m);
    float s = e0 + e1;
#pragma unroll
    for (int o = 16; o; o >>= 1) s += __shfl_xor_sync(0xffffffffu, s, o);
    float inv = 1.0f / s;
    float2 o2; o2.x = e0 * inv; o2.y = e1 * inv;
    *(float2*)&p[lane * 2] = o2;
}

// ---------------------------------------------------------------------------
// Q assembly (float4 stores)
// ---------------------------------------------------------------------------
__global__ __launch_bounds__(256)
void qasm_kernel(const float* __restrict__ theta, const float* __restrict__ pi,
                 float* __restrict__ Q)
{
    const int tok = blockIdx.x;
    __shared__ float th[NTT];
    __shared__ float spi[VV];
    __shared__ float rspi[VV];

    const int tid = threadIdx.x;
    const float* tp = theta + (size_t)tok * NTT;
    for (int i = tid; i < NTT / 4; i += 256)
        ((float4*)th)[i] = ((const float4*)tp)[i];
    if (tid < VV) {
        float p = pi[(size_t)tok * VV + tid];
        float sp = sqrtf(p);
        spi[tid] = sp;
        rspi[tid] = 1.0f / sp;
    }
    __syncthreads();

    const int i = tid >> 2;
    const int jb = (tid & 3) * 16;
    const float ri = rspi[i];
    const int offi = i * (127 - i) / 2;

    float vals[16];
    float s = 0.0f;
#pragma unroll
    for (int jj = 0; jj < 16; ++jj) {
        int j = jb + jj;
        float sv;
        if (j == i)      sv = 0.0f;
        else if (i < j)  sv = th[offi + j - i - 1];
        else             sv = th[j * (127 - j) / 2 + i - j - 1];
        float qv = sv * spi[j] * ri;
        vals[jj] = qv;
        s += qv;
    }
    s += __shfl_xor_sync(0xffffffffu, s, 1);
    s += __shfl_xor_sync(0xffffffffu, s, 2);

    if (i >= jb && i < jb + 16) vals[i - jb] = -s;

    float4* out4 = (float4*)(Q + (size_t)tok * (VV * VV) + i * VV + jb);
#pragma unroll
    for (int q = 0; q < 4; ++q)
        out4[q] = make_float4(vals[q * 4], vals[q * 4 + 1],
                              vals[q * 4 + 2], vals[q * 4 + 3]);
}

// ---------------------------------------------------------------------------
// Launch: round-9 champion with ONE edit — split(Wd) moved to head of s1 so
// it overlaps split_hi(hx c0) on S0; GEMM1 c0 gated on evWd.
// ---------------------------------------------------------------------------
#define SMEM_BIG  (2 * (2 * 128 * HROWB + 2 * 256 * HROWB))   // 221184
#define SMEM_SMALL (2 * (2 * 128 * HROWB + 2 * 64 * HROWB))   // 110592

static cudaEvent_t mk_event() {
    cudaEvent_t e; cudaEventCreateWithFlags(&e, cudaEventDisableTiming); return e;
}

extern "C" void kernel_launch(void* const* d_in, const int* in_sizes, int n_in,
                              void* d_out, int out_size)
{
    const float* hx = (const float*)d_in[0];   // (B,L,E)
    const float* Wd = (const float*)d_in[1];   // (E,E)
    const float* bd = (const float*)d_in[2];
    const float* lg = (const float*)d_in[3];
    const float* lb = (const float*)d_in[4];
    const float* Wt = (const float*)d_in[5];   // (V,E)
    const float* bt = (const float*)d_in[6];
    const float* WT = (const float*)d_in[7];   // (NT,E)
    const float* bT = (const float*)d_in[8];

    float* out = (float*)d_out;
    float* Q  = out;
    float* pi = out + (size_t)MM * VV * VV;

    float *hbuf, *thbuf;
    __half *hxh, *hh, *hl, *wdh, *wdl, *wth, *wtl, *wTh, *wTl;
    cudaGetSymbolAddress((void**)&hbuf,  g_h);
    cudaGetSymbolAddress((void**)&thbuf, g_theta);
    cudaGetSymbolAddress((void**)&hxh, g_hx_hi);
    cudaGetSymbolAddress((void**)&hh,  g_h_hi);   cudaGetSymbolAddress((void**)&hl,  g_h_lo);
    cudaGetSymbolAddress((void**)&wdh, g_Wd_hi);  cudaGetSymbolAddress((void**)&wdl, g_Wd_lo);
    cudaGetSymbolAddress((void**)&wth, g_Wt_hi);  cudaGetSymbolAddress((void**)&wtl, g_Wt_lo);
    cudaGetSymbolAddress((void**)&wTh, g_WT_hi);  cudaGetSymbolAddress((void**)&wTl, g_WT_lo);

    cudaFuncSetAttribute((const void*)gemm_hmma<1, 256, 4, 2>,
                         cudaFuncAttributeMaxDynamicSharedMemorySize, SMEM_BIG);
    cudaFuncSetAttribute((const void*)gemm_hmma<2, 256, 4, 2>,
                         cudaFuncAttributeMaxDynamicSharedMemorySize, SMEM_BIG);
    cudaFuncSetAttribute((const void*)gemm_hmma<0, 64, 2, 3>,
                         cudaFuncAttributeMaxDynamicSharedMemorySize, SMEM_SMALL);

    static cudaStream_t s1 = []{
        cudaStream_t s; cudaStreamCreateWithFlags(&s, cudaStreamNonBlocking); return s;
    }();
    static cudaEvent_t evFork = mk_event();
    static cudaEvent_t evWd = mk_event();     // Wd split (s1)  [NEW]
    static cudaEvent_t eX1 = mk_event();      // hx c1 split (s1)
    static cudaEvent_t evWT = mk_event();     // Wt+WT splits (s1)
    static cudaEvent_t e10 = mk_event();      // GEMM1 c0 (S0)
    static cudaEvent_t e11 = mk_event();      // GEMM1 c1 (S0)
    static cudaEvent_t eL0 = mk_event();      // LN c0 (s1)
    static cudaEvent_t eL1 = mk_event();      // LN c1 (s1)
    static cudaEvent_t eS1 = mk_event();      // softmax c1 (s1)
    static cudaEvent_t e30 = mk_event();      // GEMM3 c0 (S0)
    static cudaEvent_t eQ0 = mk_event();      // qasm c0 (s1)

    const size_t offE = (size_t)MC * EE;
    const size_t offT = (size_t)MC * NTT;
    const size_t offV = (size_t)MC * VV;
    const size_t offQ = (size_t)MC * VV * VV;

    // fork
    cudaEventRecord(evFork, 0);
    cudaStreamWaitEvent(s1, evFork, 0);

    // s1: Wd split FIRST (overlaps hx c0 split on S0), then hx c1, weights
    split_kernel<<<(EE * EE / 8 + 255) / 256, 256, 0, s1>>>(Wd, wdh, wdl, EE * EE / 8);
    cudaEventRecord(evWd, s1);
    split_hi_kernel<<<(MC * EE / 8 + 255) / 256, 256, 0, s1>>>(
        hx + offE, hxh + offE, MC * EE / 8);
    cudaEventRecord(eX1, s1);
    split_kernel<<<(VV * EE / 8 + 255) / 256, 256, 0, s1>>>(Wt, wth, wtl, VV * EE / 8);
    split_kernel<<<(NTT * EE / 8 + 255) / 256, 256, 0, s1>>>(WT, wTh, wTl, NTT * EE / 8);
    cudaEventRecord(evWT, s1);

    // S0: hx c0 split -> GEMM1 c0 (gated on Wd) -> GEMM1 c1
    split_hi_kernel<<<(MC * EE / 8 + 255) / 256, 256>>>(hx, hxh, MC * EE / 8);
    cudaStreamWaitEvent(0, evWd, 0);
    gemm_hmma<1, 256, 4, 2><<<dim3(MC / HBM, EE / 256), 512, SMEM_BIG>>>(
        hxh, hxh, wdh, wdl, bd, hbuf, EE, EE);
    cudaEventRecord(e10, 0);
    cudaStreamWaitEvent(0, eX1, 0);
    gemm_hmma<1, 256, 4, 2><<<dim3(MC / HBM, EE / 256), 512, SMEM_BIG>>>(
        hxh + offE, hxh + offE, wdh, wdl, bd, hbuf + offE, EE, EE);
    cudaEventRecord(e11, 0);

    // s1: LN per half chunk (c0 overlaps GEMM1 c1), then GEMM2 + softmax per half
    cudaStreamWaitEvent(s1, e10, 0);
    ln_split_kernel<<<MC, 128, 0, s1>>>(hbuf, lg, lb, hh, hl);
    cudaEventRecord(eL0, s1);
    cudaStreamWaitEvent(s1, e11, 0);
    ln_split_kernel<<<MC, 128, 0, s1>>>(hbuf + offE, lg, lb, hh + offE, hl + offE);
    cudaEventRecord(eL1, s1);
    gemm_hmma<0, 64, 2, 3><<<dim3(MC / HBM, 1), 512, SMEM_SMALL, s1>>>(
        hh, hl, wth, wtl, bt, pi, VV, EE);
    gemm_hmma<0, 64, 2, 3><<<dim3(MC / HBM, 1), 512, SMEM_SMALL, s1>>>(
        hh + offE, hl + offE, wth, wtl, bt, pi + offV, VV, EE);
    softmax_kernel<<<MC / 8, 256, 0, s1>>>(pi);
    softmax_kernel<<<MC / 8, 256, 0, s1>>>(pi + offV);
    cudaEventRecord(eS1, s1);

    // S0: GEMM3 per half chunk
    cudaStreamWaitEvent(0, evWT, 0);
    cudaStreamWaitEvent(0, eL0, 0);
    gemm_hmma<2, 256, 4, 2><<<dim3(MC / HBM, (NTT + 255) / 256), 512, SMEM_BIG>>>(
        hh, hh, wTh, wTl, bT, thbuf, NTT, EE);
    cudaEventRecord(e30, 0);
    cudaStreamWaitEvent(0, eL1, 0);
    gemm_hmma<2, 256, 4, 2><<<dim3(MC / HBM, (NTT + 255) / 256), 512, SMEM_BIG>>>(
        hh + offE, hh + offE, wTh, wTl, bT, thbuf + offT, NTT, EE);

    // s1: qasm c0 (overlaps GEMM3 c1 on S0; softmax c0 precedes in s1 order)
    cudaStreamWaitEvent(s1, e30, 0);
    qasm_kernel<<<MC, 256, 0, s1>>>(thbuf, pi, Q);
    cudaEventRecord(eQ0, s1);

    // S0: qasm c1 after GEMM3 c1 (program order) + softmax c1; then join
    cudaStreamWaitEvent(0, eS1, 0);
    qasm_kernel<<<MC, 256>>>(thbuf + offT, pi + offV, Q + offQ);
    cudaStreamWaitEvent(0, eQ0, 0);
}

// round 16
// speedup vs baseline: 1.5476x; 1.0041x over previous
#include <cuda_runtime.h>
#include <cuda_fp16.h>
#include <math.h>
#include <stdint.h>

// Problem constants
#define MM 8192           // B*L tokens
#define EE 1024
#define VV 64
#define NTT 2016
#define LN_EPS 1e-5f
#define MC (MM / 2)       // half chunk

// ---------------------------------------------------------------------------
// Scratch (device globals; no dynamic allocation allowed)
// ---------------------------------------------------------------------------
__device__ float g_h[(size_t)MM * EE];          // gelu output (pre-LN)
__device__ float g_theta[(size_t)MM * NTT];     // softplus(Theta)
__device__ __half g_hx_hi[(size_t)MM * EE];
__device__ __half g_h_hi [(size_t)MM * EE], g_h_lo [(size_t)MM * EE];
__device__ __half g_Wd_hi[EE * EE],  g_Wd_lo[EE * EE];
__device__ __half g_Wt_hi[VV * EE],  g_Wt_lo[VV * EE];
__device__ __half g_WT_hi[NTT * EE], g_WT_lo[NTT * EE];

// ---------------------------------------------------------------------------
// PTX helpers
// ---------------------------------------------------------------------------
__device__ __forceinline__ uint32_t smem_u32(const void* p) {
    return (uint32_t)__cvta_generic_to_shared(p);
}
__device__ __forceinline__ void cp16(uint32_t dst, const void* src, int sz) {
    asm volatile("cp.async.cg.shared.global [%0], [%1], 16, %2;"
                 :: "r"(dst), "l"(src), "r"(sz));
}
__device__ __forceinline__ void cp_commit() {
    asm volatile("cp.async.commit_group;" ::: "memory");
}
template<int N> __device__ __forceinline__ void cp_wait() {
    asm volatile("cp.async.wait_group %0;" :: "n"(N) : "memory");
}
__device__ __forceinline__ void ldsm4(uint32_t* r, uint32_t a) {
    asm volatile("ldmatrix.sync.aligned.m8n8.x4.shared.b16 {%0,%1,%2,%3}, [%4];"
        : "=r"(r[0]), "=r"(r[1]), "=r"(r[2]), "=r"(r[3]) : "r"(a));
}
__device__ __forceinline__ void mma16816(float* c, const uint32_t* a,
                                         uint32_t b0, uint32_t b1) {
    asm volatile(
        "mma.sync.aligned.m16n8k16.row.col.f32.f16.f16.f32 "
        "{%0,%1,%2,%3}, {%4,%5,%6,%7}, {%8,%9}, {%0,%1,%2,%3};"
        : "+f"(c[0]), "+f"(c[1]), "+f"(c[2]), "+f"(c[3])
        : "r"(a[0]), "r"(a[1]), "r"(a[2]), "r"(a[3]), "r"(b0), "r"(b1));
}

// ---------------------------------------------------------------------------
// fp32 -> (fp16 hi, fp16 lo) split, 8 elems/thread (uint4 stores)
// ---------------------------------------------------------------------------
__global__ __launch_bounds__(256)
void split_kernel(const float* __restrict__ x, __half* __restrict__ hi,
                  __half* __restrict__ lo, int n8)
{
    int i = blockIdx.x * 256 + threadIdx.x;
    if (i >= n8) return;
    float4 a = ((const float4*)x)[i * 2];
    float4 b = ((const float4*)x)[i * 2 + 1];
    float vv[8] = {a.x, a.y, a.z, a.w, b.x, b.y, b.z, b.w};
    __half h[8], l[8];
#pragma unroll
    for (int k = 0; k < 8; ++k) {
        h[k] = __float2half_rn(vv[k]);
        l[k] = __float2half_rn(vv[k] - __half2float(h[k]));
    }
    ((uint4*)hi)[i] = *(uint4*)h;
    ((uint4*)lo)[i] = *(uint4*)l;
}

// fp32 -> fp16 hi only (for A operands of 2-term GEMMs)
__global__ __launch_bounds__(256)
void split_hi_kernel(const float* __restrict__ x, __half* __restrict__ hi, int n8)
{
    int i = blockIdx.x * 256 + threadIdx.x;
    if (i >= n8) return;
    float4 a = ((const float4*)x)[i * 2];
    float4 b = ((const float4*)x)[i * 2 + 1];
    float vv[8] = {a.x, a.y, a.z, a.w, b.x, b.y, b.z, b.w};
    __half h[8];
#pragma unroll
    for (int k = 0; k < 8; ++k) h[k] = __float2half_rn(vv[k]);
    ((uint4*)hi)[i] = *(uint4*)h;
}

// ---------------------------------------------------------------------------
// fp16 multi-term HMMA GEMM:  C[M,N] = epi(A[M,K] @ B[N,K]^T + bias[N])
// BM=128, BN template (256 big / 64 narrow), BK=64, 512 threads (16 warps).
// TERMS=3: Ah*Bh + Ah*Bl + Al*Bh ; TERMS=2: Ah*Bh + Ah*Bl
// cp.async double-buffered smem, padded 144B rows.
// EPI: 0 none, 1 exact gelu, 2 softplus
// ---------------------------------------------------------------------------
#define HBM 128
#define HBK 64
#define HROWB 144                 // 64 fp16 = 128B + 16B pad

template<int EPI, int BN, int WN, int TERMS>
__global__ __launch_bounds__(512, 1)
void gemm_hmma(const __half* __restrict__ Ah, const __half* __restrict__ Al,
               const __half* __restrict__ Bh, const __half* __restrict__ Bl,
               const float* __restrict__ bias, float* __restrict__ C,
               int N, int K)
{
    constexpr int WM  = 16 / WN;
    constexpr int WTM = HBM / WM;
    constexpr int WTN = BN / WN;
    constexpr int MT  = WTM / 16;
    constexpr int NJ  = WTN / 16;

    constexpr int A_BYTES = HBM * HROWB;
    constexpr int B_BYTES = BN * HROWB;
    constexpr int AHOFF = 0;
    constexpr int ALOFF = A_BYTES;
    constexpr int BHOFF = 2 * A_BYTES;
    constexpr int BLOFF = 2 * A_BYTES + B_BYTES;
    constexpr int STAGE = 2 * A_BYTES + 2 * B_BYTES;

    extern __shared__ char hsm[];
    const uint32_t sb = smem_u32(hsm);

    const int tid  = threadIdx.x;
    const int wid  = tid >> 5;
    const int lane = tid & 31;
    const int wmb  = (wid % WM) * WTM;
    const int wnb  = (wid / WM) * WTN;
    const int bm   = blockIdx.x * HBM;
    const int bn   = blockIdx.y * BN;

    auto issue_stage = [&](int kt) {
        const uint32_t st = sb + (kt & 1) * STAGE;
        const int k0 = kt * HBK;
#pragma unroll
        for (int it = 0; it < 2; ++it) {
            int c = tid + it * 512;
            int row = c >> 3, part = c & 7;
            uint32_t dst = (uint32_t)(row * HROWB + part * 16);
            size_t src = (size_t)(bm + row) * K + k0 + part * 8;
            cp16(st + AHOFF + dst, Ah + src, 16);
            if (TERMS == 3) cp16(st + ALOFF + dst, Al + src, 16);
        }
#pragma unroll
        for (int it = 0; it < BN / 64; ++it) {
            int c = tid + it * 512;
            int row = c >> 3, part = c & 7;
            int gn = bn + row;
            int valid = (gn < N) ? 16 : 0;
            int gnc = (gn < N) ? gn : 0;
            uint32_t dst = (uint32_t)(row * HROWB + part * 16);
            size_t src = (size_t)gnc * K + k0 + part * 8;
            cp16(st + BHOFF + dst, Bh + src, valid);
            cp16(st + BLOFF + dst, Bl + src, valid);
        }
        cp_commit();
    };

    float acc[MT][WTN / 8][4];
#pragma unroll
    for (int i = 0; i < MT; ++i)
#pragma unroll
        for (int j = 0; j < WTN / 8; ++j)
#pragma unroll
            for (int q = 0; q < 4; ++q) acc[i][j][q] = 0.0f;

    issue_stage(0);

    const int nk = K / HBK;
    const int a_row = lane & 15;
    const int a_cb  = (lane >> 4) * 16;
    const int b_row = ((lane >> 4) ? 8 : 0) + (lane & 7);
    const int b_cb  = (((lane >> 3) & 1) ? 16 : 0);

    for (int kt = 0; kt < nk; ++kt) {
        if (kt + 1 < nk) { issue_stage(kt + 1); cp_wait<1>(); }
        else             { cp_wait<0>(); }
        __syncthreads();
        const uint32_t st = sb + (kt & 1) * STAGE;

#pragma unroll
        for (int ks = 0; ks < 4; ++ks) {
            uint32_t aH[MT][4], aL[MT][4];
#pragma unroll
            for (int mt = 0; mt < MT; ++mt) {
                const uint32_t ao = st + (uint32_t)((wmb + mt * 16 + a_row) * HROWB
                                                    + ks * 32 + a_cb);
                ldsm4(aH[mt], ao + AHOFF);
                if (TERMS == 3) ldsm4(aL[mt], ao + ALOFF);
            }
#pragma unroll
            for (int jj = 0; jj < NJ; ++jj) {
                const uint32_t bo = st + (uint32_t)((wnb + jj * 16 + b_row) * HROWB
                                                    + ks * 32 + b_cb);
                uint32_t bH[4], bL[4];
                ldsm4(bH, bo + BHOFF);
                ldsm4(bL, bo + BLOFF);
#pragma unroll
                for (int mt = 0; mt < MT; ++mt) {
#pragma unroll
                    for (int sub = 0; sub < 2; ++sub) {
                        float* c = acc[mt][jj * 2 + sub];
                        mma16816(c, aH[mt], bH[sub * 2], bH[sub * 2 + 1]);
                        mma16816(c, aH[mt], bL[sub * 2], bL[sub * 2 + 1]);
                        if (TERMS == 3)
                            mma16816(c, aL[mt], bH[sub * 2], bH[sub * 2 + 1]);
                    }
                }
            }
        }
        __syncthreads();
    }

    // epilogue
#pragma unroll
    for (int mt = 0; mt < MT; ++mt) {
        const int row = bm + wmb + mt * 16 + (lane >> 2);
#pragma unroll
        for (int nt = 0; nt < WTN / 8; ++nt) {
            const int col = bn + wnb + nt * 8 + (lane & 3) * 2;
            if (col < N) {
                const float b0 = bias[col], b1 = bias[col + 1];
                float vals[4];
                vals[0] = acc[mt][nt][0] + b0;
                vals[1] = acc[mt][nt][1] + b1;
                vals[2] = acc[mt][nt][2] + b0;
                vals[3] = acc[mt][nt][3] + b1;
#pragma unroll
                for (int q = 0; q < 4; ++q) {
                    float x = vals[q];
                    if (EPI == 1) {
                        x = 0.5f * x * (1.0f + erff(x * 0.70710678118654752440f));
                    } else if (EPI == 2) {
                        x = fmaxf(x, 0.0f) + log1pf(expf(-fabsf(x)));
                    }
                    vals[q] = x;
                }
                *(float2*)&C[(size_t)row * N + col]       = make_float2(vals[0], vals[1]);
                *(float2*)&C[(size_t)(row + 8) * N + col] = make_float2(vals[2], vals[3]);
            }
        }
    }
}

// ---------------------------------------------------------------------------
// LayerNorm over rows of E=1024, fused with fp16 hi/lo split of the output.
// ---------------------------------------------------------------------------
__global__ __launch_bounds__(128)
void ln_split_kernel(const float* __restrict__ h, const float* __restrict__ g,
                     const float* __restrict__ b,
                     __half* __restrict__ hi, __half* __restrict__ lo)
{
    const int row = blockIdx.x;
    const int tid = threadIdx.x;
    const int wid = tid >> 5;
    const float* p = h + (size_t)row * EE;

    float4 v0 = ((const float4*)p)[tid * 2];
    float4 v1 = ((const float4*)p)[tid * 2 + 1];
    float v[8] = {v0.x, v0.y, v0.z, v0.w, v1.x, v1.y, v1.z, v1.w};

    __shared__ float red_a[4], red_b[4];

    float s = 0.0f;
#pragma unroll
    for (int k = 0; k < 8; ++k) s += v[k];
#pragma unroll
    for (int o = 16; o; o >>= 1) s += __shfl_xor_sync(0xffffffffu, s, o);
    if ((tid & 31) == 0) red_a[wid] = s;
    __syncthreads();
    const float mu = (red_a[0] + red_a[1] + red_a[2] + red_a[3]) * (1.0f / EE);

    float d[8];
    float s2 = 0.0f;
#pragma unroll
    for (int k = 0; k < 8; ++k) { d[k] = v[k] - mu; s2 += d[k] * d[k]; }
#pragma unroll
    for (int o = 16; o; o >>= 1) s2 += __shfl_xor_sync(0xffffffffu, s2, o);
    if ((tid & 31) == 0) red_b[wid] = s2;
    __syncthreads();
    const float rstd = rsqrtf((red_b[0] + red_b[1] + red_b[2] + red_b[3]) * (1.0f / EE)
                              + LN_EPS);

    const int c = tid * 8;
    float4 g0 = *(const float4*)&g[c], g1 = *(const float4*)&g[c + 4];
    float4 b0 = *(const float4*)&b[c], b1 = *(const float4*)&b[c + 4];
    float gg[8] = {g0.x, g0.y, g0.z, g0.w, g1.x, g1.y, g1.z, g1.w};
    float bb[8] = {b0.x, b0.y, b0.z, b0.w, b1.x, b1.y, b1.z, b1.w};

    __half hb[8], lb8[8];
#pragma unroll
    for (int k = 0; k < 8; ++k) {
        float o = d[k] * rstd * gg[k] + bb[k];
        hb[k]  = __float2half_rn(o);
        lb8[k] = __float2half_rn(o - __half2float(hb[k]));
    }
    ((uint4*)(hi + (size_t)row * EE))[tid] = *(uint4*)hb;
    ((uint4*)(lo + (size_t)row * EE))[tid] = *(uint4*)lb8;
}

// ---------------------------------------------------------------------------
// Softmax (in-place) over rows of V=64. One warp per row, 8 rows per block.
// ---------------------------------------------------------------------------
__global__ __launch_bounds__(256)
void softmax_kernel(float* __restrict__ logits)
{
    const int row = blockIdx.x * 8 + (threadIdx.x >> 5);
    const int lane = threadIdx.x & 31;
    float* p = logits + (size_t)row * VV;

    float2 v = *(const float2*)&p[lane * 2];
    float m = fmaxf(v.x, v.y);
#pragma unroll
    for (int o = 16; o; o >>= 1) m = fmaxf(m, __shfl_xor_sync(0xffffffffu, m, o));
    float e0 = expf(v.x - m), e1 = expf(v.y - m);
    float s = e0 + e1;
#pragma unroll
    for (int o = 16; o; o >>= 1) s += __shfl_xor_sync(0xffffffffu, s, o);
    float inv = 1.0f / s;
    float2 o2; o2.x = e0 * inv; o2.y = e1 * inv;
    *(float2*)&p[lane * 2] = o2;
}

// ---------------------------------------------------------------------------
// Q assembly (float4 stores)
// ---------------------------------------------------------------------------
__global__ __launch_bounds__(256)
void qasm_kernel(const float* __restrict__ theta, const float* __restrict__ pi,
                 float* __restrict__ Q)
{
    const int tok = blockIdx.x;
    __shared__ float th[NTT];
    __shared__ float spi[VV];
    __shared__ float rspi[VV];

    const int tid = threadIdx.x;
    const float* tp = theta + (size_t)tok * NTT;
    for (int i = tid; i < NTT / 4; i += 256)
        ((float4*)th)[i] = ((const float4*)tp)[i];
    if (tid < VV) {
        float p = pi[(size_t)tok * VV + tid];
        float sp = sqrtf(p);
        spi[tid] = sp;
        rspi[tid] = 1.0f / sp;
    }
    __syncthreads();

    const int i = tid >> 2;
    const int jb = (tid & 3) * 16;
    const float ri = rspi[i];
    const int offi = i * (127 - i) / 2;

    float vals[16];
    float s = 0.0f;
#pragma unroll
    for (int jj = 0; jj < 16; ++jj) {
        int j = jb + jj;
        float sv;
        if (j == i)      sv = 0.0f;
        else if (i < j)  sv = th[offi + j - i - 1];
        else             sv = th[j * (127 - j) / 2 + i - j - 1];
        float qv = sv * spi[j] * ri;
        vals[jj] = qv;
        s += qv;
    }
    s += __shfl_xor_sync(0xffffffffu, s, 1);
    s += __shfl_xor_sync(0xffffffffu, s, 2);

    if (i >= jb && i < jb + 16) vals[i - jb] = -s;

    float4* out4 = (float4*)(Q + (size_t)tok * (VV * VV) + i * VV + jb);
#pragma unroll
    for (int q = 0; q < 4; ++q)
        out4[q] = make_float4(vals[q * 4], vals[q * 4 + 1],
                              vals[q * 4 + 2], vals[q * 4 + 3]);
}

// ---------------------------------------------------------------------------
// Launch: R15 champion with ONE s1 reorder — GEMM2 c0 + softmax c0 moved
// between LN c0 and LN c1 so they hide under GEMM1 c1 instead of GEMM3 c0.
// ---------------------------------------------------------------------------
#define SMEM_BIG  (2 * (2 * 128 * HROWB + 2 * 256 * HROWB))   // 221184
#define SMEM_SMALL (2 * (2 * 128 * HROWB + 2 * 64 * HROWB))   // 110592

static cudaEvent_t mk_event() {
    cudaEvent_t e; cudaEventCreateWithFlags(&e, cudaEventDisableTiming); return e;
}

extern "C" void kernel_launch(void* const* d_in, const int* in_sizes, int n_in,
                              void* d_out, int out_size)
{
    const float* hx = (const float*)d_in[0];   // (B,L,E)
    const float* Wd = (const float*)d_in[1];   // (E,E)
    const float* bd = (const float*)d_in[2];
    const float* lg = (const float*)d_in[3];
    const float* lb = (const float*)d_in[4];
    const float* Wt = (const float*)d_in[5];   // (V,E)
    const float* bt = (const float*)d_in[6];
    const float* WT = (const float*)d_in[7];   // (NT,E)
    const float* bT = (const float*)d_in[8];

    float* out = (float*)d_out;
    float* Q  = out;
    float* pi = out + (size_t)MM * VV * VV;

    float *hbuf, *thbuf;
    __half *hxh, *hh, *hl, *wdh, *wdl, *wth, *wtl, *wTh, *wTl;
    cudaGetSymbolAddress((void**)&hbuf,  g_h);
    cudaGetSymbolAddress((void**)&thbuf, g_theta);
    cudaGetSymbolAddress((void**)&hxh, g_hx_hi);
    cudaGetSymbolAddress((void**)&hh,  g_h_hi);   cudaGetSymbolAddress((void**)&hl,  g_h_lo);
    cudaGetSymbolAddress((void**)&wdh, g_Wd_hi);  cudaGetSymbolAddress((void**)&wdl, g_Wd_lo);
    cudaGetSymbolAddress((void**)&wth, g_Wt_hi);  cudaGetSymbolAddress((void**)&wtl, g_Wt_lo);
    cudaGetSymbolAddress((void**)&wTh, g_WT_hi);  cudaGetSymbolAddress((void**)&wTl, g_WT_lo);

    cudaFuncSetAttribute((const void*)gemm_hmma<1, 256, 4, 2>,
                         cudaFuncAttributeMaxDynamicSharedMemorySize, SMEM_BIG);
    cudaFuncSetAttribute((const void*)gemm_hmma<2, 256, 4, 2>,
                         cudaFuncAttributeMaxDynamicSharedMemorySize, SMEM_BIG);
    cudaFuncSetAttribute((const void*)gemm_hmma<0, 64, 2, 3>,
                         cudaFuncAttributeMaxDynamicSharedMemorySize, SMEM_SMALL);

    static cudaStream_t s1 = []{
        cudaStream_t s; cudaStreamCreateWithFlags(&s, cudaStreamNonBlocking); return s;
    }();
    static cudaEvent_t evFork = mk_event();
    static cudaEvent_t evWd = mk_event();     // Wd split (s1)
    static cudaEvent_t eX1 = mk_event();      // hx c1 split (s1)
    static cudaEvent_t evWT = mk_event();     // Wt+WT splits (s1)
    static cudaEvent_t e10 = mk_event();      // GEMM1 c0 (S0)
    static cudaEvent_t e11 = mk_event();      // GEMM1 c1 (S0)
    static cudaEvent_t eL0 = mk_event();      // LN c0 (s1)
    static cudaEvent_t eL1 = mk_event();      // LN c1 (s1)
    static cudaEvent_t eS1 = mk_event();      // softmax c1 (s1)
    static cudaEvent_t e30 = mk_event();      // GEMM3 c0 (S0)
    static cudaEvent_t eQ0 = mk_event();      // qasm c0 (s1)

    const size_t offE = (size_t)MC * EE;
    const size_t offT = (size_t)MC * NTT;
    const size_t offV = (size_t)MC * VV;
    const size_t offQ = (size_t)MC * VV * VV;

    // fork
    cudaEventRecord(evFork, 0);
    cudaStreamWaitEvent(s1, evFork, 0);

    // s1: Wd split FIRST (overlaps hx c0 split on S0), then hx c1, weights
    split_kernel<<<(EE * EE / 8 + 255) / 256, 256, 0, s1>>>(Wd, wdh, wdl, EE * EE / 8);
    cudaEventRecord(evWd, s1);
    split_hi_kernel<<<(MC * EE / 8 + 255) / 256, 256, 0, s1>>>(
        hx + offE, hxh + offE, MC * EE / 8);
    cudaEventRecord(eX1, s1);
    split_kernel<<<(VV * EE / 8 + 255) / 256, 256, 0, s1>>>(Wt, wth, wtl, VV * EE / 8);
    split_kernel<<<(NTT * EE / 8 + 255) / 256, 256, 0, s1>>>(WT, wTh, wTl, NTT * EE / 8);
    cudaEventRecord(evWT, s1);

    // S0: hx c0 split -> GEMM1 c0 (gated on Wd) -> GEMM1 c1
    split_hi_kernel<<<(MC * EE / 8 + 255) / 256, 256>>>(hx, hxh, MC * EE / 8);
    cudaStreamWaitEvent(0, evWd, 0);
    gemm_hmma<1, 256, 4, 2><<<dim3(MC / HBM, EE / 256), 512, SMEM_BIG>>>(
        hxh, hxh, wdh, wdl, bd, hbuf, EE, EE);
    cudaEventRecord(e10, 0);
    cudaStreamWaitEvent(0, eX1, 0);
    gemm_hmma<1, 256, 4, 2><<<dim3(MC / HBM, EE / 256), 512, SMEM_BIG>>>(
        hxh + offE, hxh + offE, wdh, wdl, bd, hbuf + offE, EE, EE);
    cudaEventRecord(e11, 0);

    // s1: LN c0, then GEMM2 c0 + softmax c0 (hidden under GEMM1 c1 window),
    // then LN c1, GEMM2 c1 + softmax c1.
    cudaStreamWaitEvent(s1, e10, 0);
    ln_split_kernel<<<MC, 128, 0, s1>>>(hbuf, lg, lb, hh, hl);
    cudaEventRecord(eL0, s1);
    gemm_hmma<0, 64, 2, 3><<<dim3(MC / HBM, 1), 512, SMEM_SMALL, s1>>>(
        hh, hl, wth, wtl, bt, pi, VV, EE);
    softmax_kernel<<<MC / 8, 256, 0, s1>>>(pi);
    cudaStreamWaitEvent(s1, e11, 0);
    ln_split_kernel<<<MC, 128, 0, s1>>>(hbuf + offE, lg, lb, hh + offE, hl + offE);
    cudaEventRecord(eL1, s1);
    gemm_hmma<0, 64, 2, 3><<<dim3(MC / HBM, 1), 512, SMEM_SMALL, s1>>>(
        hh + offE, hl + offE, wth, wtl, bt, pi + offV, VV, EE);
    softmax_kernel<<<MC / 8, 256, 0, s1>>>(pi + offV);
    cudaEventRecord(eS1, s1);

    // S0: GEMM3 per half chunk
    cudaStreamWaitEvent(0, evWT, 0);
    cudaStreamWaitEvent(0, eL0, 0);
    gemm_hmma<2, 256, 4, 2><<<dim3(MC / HBM, (NTT + 255) / 256), 512, SMEM_BIG>>>(
        hh, hh, wTh, wTl, bT, thbuf, NTT, EE);
    cudaEventRecord(e30, 0);
    cudaStreamWaitEvent(0, eL1, 0);
    gemm_hmma<2, 256, 4, 2><<<dim3(MC / HBM, (NTT + 255) / 256), 512, SMEM_BIG>>>(
        hh + offE, hh + offE, wTh, wTl, bT, thbuf + offT, NTT, EE);

    // s1: qasm c0 (overlaps GEMM3 c1 on S0; softmax c0 precedes in s1 order)
    cudaStreamWaitEvent(s1, e30, 0);
    qasm_kernel<<<MC, 256, 0, s1>>>(thbuf, pi, Q);
    cudaEventRecord(eQ0, s1);

    // S0: qasm c1 after GEMM3 c1 (program order) + softmax c1; then join
    cudaStreamWaitEvent(0, eS1, 0);
    qasm_kernel<<<MC, 256>>>(thbuf + offT, pi + offV, Q + offQ);
    cudaStreamWaitEvent(0, eQ0, 0);
}